// round 12
// baseline (speedup 1.0000x reference)
#include <cuda_runtime.h>
#include <cuda_bf16.h>
#include <cuda_fp16.h>
#include <cuda_fp8.h>
#include <math.h>
#include <stdint.h>

#define BB 8
#define SS 4096
#define DD 1024
#define FF 512
#define M_TOTAL (BB*SS)   // 32768
#define MAXP 8
#define NKT 16            // 1024/64 k-tiles
#define KSP 8             // split-k factor for patch GEMM
#define W1SCALE 64.0f
#define W1INV   0.015625f

// ---------------- device scratch ----------------
__device__ uint32_t g_Xq[(size_t)M_TOTAL * (DD/4)];      // 32 MB e4m3 tile-linear
__device__ uint32_t g_Bpk[NKT * FF * 16];                // 512 KB e4m3 tile-linear
__device__ float g_partial[M_TOTAL*8];
__device__ float g_norm2[M_TOTAL];
__device__ float g_dot[M_TOTAL];
__device__ float g_pooled[BB*MAXP*DD];
__device__ float g_ppart[KSP*BB*MAXP*DD];                // 2 MB split-k partials
__device__ int g_first, g_last;

// ---------------- helpers ----------------
__device__ __forceinline__ uint32_t s2u(const void* p){
    uint32_t a;
    asm("{ .reg .u64 t; cvta.to.shared.u64 t, %1; cvt.u32.u64 %0, t; }" : "=r"(a) : "l"(p));
    return a;
}
__device__ __forceinline__ void cp16(uint32_t dst, const void* src){
    asm volatile("cp.async.cg.shared.global [%0], [%1], 16;" :: "r"(dst), "l"(src) : "memory");
}
__device__ __forceinline__ void cp_commit(){ asm volatile("cp.async.commit_group;" ::: "memory"); }
__device__ __forceinline__ void cp_wait0(){ asm volatile("cp.async.wait_group 0;" ::: "memory"); }
__device__ __forceinline__ void cp_wait2(){ asm volatile("cp.async.wait_group 2;" ::: "memory"); }

__device__ __forceinline__ void mmaqh(unsigned* d, const unsigned* a, unsigned b0, unsigned b1){
    asm volatile(
      "mma.sync.aligned.m16n8k32.row.col.f16.e4m3.e4m3.f16 "
      "{%0,%1}, {%2,%3,%4,%5}, {%6,%7}, {%0,%1};\n"
      : "+r"(d[0]), "+r"(d[1])
      : "r"(a[0]), "r"(a[1]), "r"(a[2]), "r"(a[3]), "r"(b0), "r"(b1));
}
__device__ __forceinline__ void ldsm4(unsigned* r, uint32_t addr){
    asm volatile("ldmatrix.sync.aligned.m8n8.x4.shared.b16 {%0,%1,%2,%3}, [%4];"
                 : "=r"(r[0]), "=r"(r[1]), "=r"(r[2]), "=r"(r[3]) : "r"(addr));
}
__device__ __forceinline__ uint32_t pack4_e4m3(float x, float y, float z, float w){
    __nv_fp8x2_storage_t p0 = __nv_cvt_float2_to_fp8x2(make_float2(x, y), __NV_SATFINITE, __NV_E4M3);
    __nv_fp8x2_storage_t p1 = __nv_cvt_float2_to_fp8x2(make_float2(z, w), __NV_SATFINITE, __NV_E4M3);
    return ((uint32_t)p1 << 16) | (uint32_t)p0;
}

// ============ prep: pack 64*W1 -> [kt][n][64B] e4m3 rows (+ init) ==========
__global__ void k_prep(const float* __restrict__ W1){
    int idx = blockIdx.x*256 + threadIdx.x;    // 131072 words
    if (idx == 0){ g_first = 0x7fffffff; g_last = -1; }
    if (idx >= NKT*FF*16) return;
    int kt = idx >> 13;
    int wo = idx & 8191;
    int n  = wo >> 4;
    int ww = wo & 15;
    int k  = kt*64 + 4*ww;
    g_Bpk[idx] = pack4_e4m3(W1[(size_t)k*FF + n]     * W1SCALE,
                            W1[(size_t)(k+1)*FF + n] * W1SCALE,
                            W1[(size_t)(k+2)*FF + n] * W1SCALE,
                            W1[(size_t)(k+3)*FF + n] * W1SCALE);
}

// ===== k_cos: norms + adjacent dots + f32->e4m3 tile-linear conversion =====
__global__ __launch_bounds__(256) void k_cos(const float* __restrict__ X){
    int tid = threadIdx.x, w = tid>>5, lane = tid&31;
    int base = blockIdx.x*32 + w*4;
    const float4* xp = (const float4*)X;
    float4 a[8];
    size_t rb = (size_t)base*(DD/4);
    #pragma unroll
    for (int t = 0; t < 8; t++) a[t] = xp[rb + lane + t*32];
    #pragma unroll
    for (int j = 0; j < 4; j++){
        int s = base + j;
        {
            int mtile = s >> 7, rl = s & 127;
            #pragma unroll
            for (int t = 0; t < 8; t++){
                int kt = (lane >> 4) + 2*t;
                int wi = lane & 15;
                uint32_t q = pack4_e4m3(a[t].x, a[t].y, a[t].z, a[t].w);
                size_t di = ((size_t)(mtile*NKT + kt)*128 + rl)*16 + wi;
                g_Xq[di] = q;
            }
        }
        float n2 = 0.f;
        #pragma unroll
        for (int t = 0; t < 8; t++)
            n2 += a[t].x*a[t].x + a[t].y*a[t].y + a[t].z*a[t].z + a[t].w*a[t].w;
        bool pv = ((s & (SS-1)) != (SS-1));
        float4 b[8];
        float dt = 0.f;
        if (pv){
            size_t rb2 = (size_t)(s+1)*(DD/4);
            #pragma unroll
            for (int t = 0; t < 8; t++){
                b[t] = xp[rb2 + lane + t*32];
                dt += a[t].x*b[t].x + a[t].y*b[t].y + a[t].z*b[t].z + a[t].w*b[t].w;
            }
        }
        #pragma unroll
        for (int o = 16; o > 0; o >>= 1){
            n2 += __shfl_xor_sync(0xffffffffu, n2, o);
            dt += __shfl_xor_sync(0xffffffffu, dt, o);
        }
        if (lane == 0){ g_norm2[s] = n2; if (pv) g_dot[s] = dt; }
        #pragma unroll
        for (int t = 0; t < 8; t++) a[t] = b[t];
    }
}

// ================= segment pooling: parallel mask scan + MLP sum ===========
__global__ __launch_bounds__(256) void k_pool(const float* __restrict__ X,
                                              const int* __restrict__ Mk){
    __shared__ float ssum[MAXP*DD];   // 32 KB
    __shared__ int   sseg[256];
    __shared__ int   scnt[MAXP];
    __shared__ int   swsum[8];
    int b = blockIdx.x;
    int tid = threadIdx.x, w = tid>>5, lane = tid&31;
    for (int i = tid; i < MAXP*DD; i += 256) ssum[i] = 0.f;
    if (tid < MAXP) scnt[tid] = 0;
    __syncthreads();
    const float* xb = X + (size_t)b*SS*DD;
    const int*   mb = Mk + (size_t)b*SS;

    int seg0 = 0;
    for (int base = 0; base < SS && seg0 < MAXP; base += 256){
        int m = mb[base + tid] != 0 ? 1 : 0;
        // inclusive warp scan
        int v = m;
        #pragma unroll
        for (int o = 1; o < 32; o <<= 1){
            int n = __shfl_up_sync(0xffffffffu, v, o);
            if (lane >= o) v += n;
        }
        if (lane == 31) swsum[w] = v;
        __syncthreads();
        int woff = 0;
        #pragma unroll
        for (int j = 0; j < 8; j++) woff += (j < w) ? swsum[j] : 0;
        int seg = seg0 + woff + v - m;      // exclusive prefix = segment id
        sseg[tid] = seg;
        if (seg < MAXP) atomicAdd(&scnt[seg], 1);
        int total = 0;
        #pragma unroll
        for (int j = 0; j < 8; j++) total += swsum[j];
        __syncthreads();
        // accumulate rows of this chunk (seg nondecreasing -> break at MAXP)
        for (int s = 0; s < 256; s++){
            int p = sseg[s];
            if (p >= MAXP) break;
            #pragma unroll
            for (int j = 0; j < 4; j++){
                int d = tid + j*256;
                ssum[p*DD + d] += xb[(size_t)(base + s)*DD + d];
            }
        }
        seg0 += total;
        __syncthreads();
    }
    #pragma unroll
    for (int p = 0; p < MAXP; p++){
        float inv = 1.f / (float)max(scnt[p], 1);
        #pragma unroll
        for (int j = 0; j < 4; j++){
            int d = tid + j*256;
            g_pooled[((size_t)b*MAXP + p)*DD + d] = ssum[p*DD + d] * inv;
        }
    }
}

// ===== GEMM: 4-buffer cp.async pipeline + fp8 QMMA f16acc, 2 CTAs/SM =======
#define ROWB 80
#define TILEB (128*ROWB)
#define SM_B1OFF (8*TILEB)
#define SM_W2OFF (SM_B1OFF + 2048)
#define SM_DYN   (SM_W2OFF + 2048)
__global__ __launch_bounds__(256, 2) void k_gemm(const float* __restrict__ b1,
                                                 const float* __restrict__ w2){
    extern __shared__ __align__(16) char dsm[];
    char* Abuf[4]; char* Bbuf[4];
    #pragma unroll
    for (int b = 0; b < 4; b++){
        Abuf[b] = dsm + b*TILEB;
        Bbuf[b] = dsm + 4*TILEB + b*TILEB;
    }
    float* b1s = (float*)(dsm + SM_B1OFF);
    float* w2s = (float*)(dsm + SM_W2OFF);

    const int nc  = blockIdx.x;
    const int mt0 = blockIdx.y;
    const int m0  = mt0 * 128;
    const int n0  = nc * 128;
    const int tid = threadIdx.x;
    const int warp = tid >> 5, lane = tid & 31;
    const int warpM = warp >> 1, warpN = warp & 1;
    const int lr = lane >> 2, qc = lane & 3;

    #pragma unroll
    for (int j = 0; j < 2; j++){
        b1s[tid + j*256] = b1[tid + j*256];
        w2s[tid + j*256] = w2[tid + j*256];
    }

    const int arow = warpM*32 + (lane & 7) + ((lane >> 3) & 1)*8;
    const int abyt = ((lane >> 4) & 1)*16;
    const int brow = warpN*64 + (lane & 7) + ((lane >> 4) & 1)*8;
    const int bbyt = ((lane >> 3) & 1)*16;
    const uint32_t aoff = (uint32_t)(arow*ROWB + abyt);
    const uint32_t boff = (uint32_t)(brow*ROWB + bbyt);

    const char* xsrc = (const char*)g_Xq + (size_t)mt0 * (NKT*128*64);
    const char* bsrc = (const char*)g_Bpk;

    auto stage = [&](int kt, int buf){
        uint32_t ad = s2u(Abuf[buf]);
        uint32_t bd = s2u(Bbuf[buf]);
        const char* xs = xsrc + (size_t)kt*(128*64);
        const char* bs = bsrc + ((size_t)kt*512 + n0)*64;
        #pragma unroll
        for (int i = 0; i < 2; i++){
            int g = tid + i*256;
            int row = g >> 2, cb = (g & 3)*16;
            cp16(ad + row*ROWB + cb, xs + row*64 + cb);
        }
        #pragma unroll
        for (int i = 0; i < 2; i++){
            int g = tid + i*256;
            int row = g >> 2, cb = (g & 3)*16;
            cp16(bd + row*ROWB + cb, bs + row*64 + cb);
        }
    };

    unsigned int acc[2][8][2];
    #pragma unroll
    for (int mt=0; mt<2; mt++)
      #pragma unroll
      for (int nt=0; nt<8; nt++){ acc[mt][nt][0] = 0u; acc[mt][nt][1] = 0u; }

    stage(0, 0); cp_commit();
    stage(1, 1); cp_commit();

    for (int kt = 0; kt < NKT; kt++){
        int buf = kt & 3;
        if (kt + 2 < NKT){
            stage(kt + 2, (kt + 2) & 3);
            cp_commit();
            cp_wait2();
        } else {
            cp_wait0();
        }
        __syncthreads();
        const uint32_t aA = s2u(Abuf[buf]) + aoff;
        const uint32_t bA = s2u(Bbuf[buf]) + boff;
        #pragma unroll
        for (int ks = 0; ks < 2; ks++){
            unsigned int a[2][4];
            ldsm4(a[0], aA + ks*32);
            ldsm4(a[1], aA + 16*ROWB + ks*32);
            unsigned int b[8][2];
            #pragma unroll
            for (int ntp = 0; ntp < 4; ntp++){
                unsigned int r[4];
                ldsm4(r, bA + ntp*16*ROWB + ks*32);
                b[2*ntp  ][0] = r[0]; b[2*ntp  ][1] = r[1];
                b[2*ntp+1][0] = r[2]; b[2*ntp+1][1] = r[3];
            }
            #pragma unroll
            for (int nt = 0; nt < 8; nt++){
                mmaqh(acc[0][nt], a[0], b[nt][0], b[nt][1]);
                mmaqh(acc[1][nt], a[1], b[nt][0], b[nt][1]);
            }
        }
    }

    float b1r[16], w2r[16];
    #pragma unroll
    for (int nt = 0; nt < 8; nt++){
        #pragma unroll
        for (int e = 0; e < 2; e++){
            int n = n0 + warpN*64 + nt*8 + qc*2 + e;
            b1r[nt*2+e] = b1s[n];
            w2r[nt*2+e] = w2s[n];
        }
    }
    #pragma unroll
    for (int mt = 0; mt < 2; mt++){
        float sA = 0.f, sB = 0.f;
        #pragma unroll
        for (int nt = 0; nt < 8; nt++){
            float2 vA = __half22float2(*(__half2*)&acc[mt][nt][0]);
            float2 vB = __half22float2(*(__half2*)&acc[mt][nt][1]);
            sA += fmaxf(vA.x * W1INV + b1r[nt*2+0], 0.f) * w2r[nt*2+0];
            sA += fmaxf(vA.y * W1INV + b1r[nt*2+1], 0.f) * w2r[nt*2+1];
            sB += fmaxf(vB.x * W1INV + b1r[nt*2+0], 0.f) * w2r[nt*2+0];
            sB += fmaxf(vB.y * W1INV + b1r[nt*2+1], 0.f) * w2r[nt*2+1];
        }
        sA += __shfl_xor_sync(0xffffffffu, sA, 1);
        sA += __shfl_xor_sync(0xffffffffu, sA, 2);
        sB += __shfl_xor_sync(0xffffffffu, sB, 1);
        sB += __shfl_xor_sync(0xffffffffu, sB, 2);
        if (qc == 0){
            int rA = m0 + warpM*32 + mt*16 + lr;
            g_partial[(size_t)rA*8     + nc*2 + warpN] = sA;
            g_partial[(size_t)(rA+8)*8 + nc*2 + warpN] = sB;
        }
    }
}

// ======== patch split-k pass 1: partial[ks][b][p][o] over 128-k chunk ======
__global__ __launch_bounds__(128) void k_patch1(const float* __restrict__ Pw){
    __shared__ float ps[MAXP*128];
    int oc = blockIdx.x, b = blockIdx.y, ks = blockIdx.z;
    int tid = threadIdx.x;
    #pragma unroll
    for (int j = 0; j < 8; j++){
        int e = tid + j*128;
        int p = e >> 7, d = e & 127;
        ps[p*128 + d] = g_pooled[((size_t)b*MAXP + p)*DD + ks*128 + d];
    }
    __syncthreads();
    int o = oc*128 + tid;
    float acc[MAXP];
    #pragma unroll
    for (int p = 0; p < MAXP; p++) acc[p] = 0.f;
    const float* pw = Pw + (size_t)(ks*128)*DD + o;
    #pragma unroll 4
    for (int d = 0; d < 128; d++){
        float w = pw[(size_t)d*DD];
        #pragma unroll
        for (int p = 0; p < MAXP; p++) acc[p] += ps[p*128 + d] * w;
    }
    #pragma unroll
    for (int p = 0; p < MAXP; p++)
        g_ppart[(((size_t)ks*BB + b)*MAXP + p)*DD + o] = acc[p];
}

// ======== fused: rules (blocks 0..127) + patch split-k reduce (128..383) ===
__global__ __launch_bounds__(256) void k_rule(const float* __restrict__ b2,
                                              const float* __restrict__ Pb,
                                              float* __restrict__ out){
    if (blockIdx.x >= 128){
        int i = (blockIdx.x - 128)*256 + threadIdx.x;   // 65536 outputs
        int o = i & (DD-1);
        float s = Pb[o];
        #pragma unroll
        for (int ks = 0; ks < KSP; ks++)
            s += g_ppart[(size_t)ks*(BB*MAXP*DD) + i];
        out[i] = s;
        return;
    }
    __shared__ float sc[258];
    int base = blockIdx.x*256;
    int tid = threadIdx.x;
    int i = base + tid;
    float bb = __ldg(b2);
    {
        float l = bb;
        #pragma unroll
        for (int j = 0; j < 8; j++) l += g_partial[(size_t)i*8 + j];
        sc[tid + 2] = 1.f / (1.f + expf(-l));
    }
    if (tid < 2){
        int r = base - 2 + tid;
        float v = 0.f;
        if (r >= 0){
            float l = bb;
            #pragma unroll
            for (int j = 0; j < 8; j++) l += g_partial[(size_t)r*8 + j];
            v = 1.f / (1.f + expf(-l));
        }
        sc[tid] = v;
    }
    __syncthreads();
    int t = i & (SS-1);
    if (t < 2) return;
    float s0 = sc[tid+2], s1 = sc[tid+1], s2 = sc[tid];
    bool run = (s0 > 0.7f) && (s1 > 0.7f) && (s2 > 0.7f);
    float na = fmaxf(sqrtf(g_norm2[i-1]), 1e-8f);
    float nb = fmaxf(sqrtf(g_norm2[i]),   1e-8f);
    float cosv = g_dot[i-1] / (na * nb);
    bool cr = (cosv < 0.3f) && (s0 > 0.5f);
    if (run || cr){
        atomicMin(&g_first, t);
        atomicMax(&g_last,  t);
    }
}

// ================= finalize bounds =========================================
__global__ void k_final(float* __restrict__ out, int out_size){
    if (threadIdx.x == 0 && blockIdx.x == 0){
        int f = g_first, l = g_last;
        float s0 = -1.f, s1 = -1.f;
        if (f != 0x7fffffff){
            s0 = (float)max(0, f - 2);
            s1 = (float)min(SS - 1, l + 2);
        }
        if (out_size >= BB*MAXP*DD + 2){
            out[BB*MAXP*DD + 0] = s0;
            out[BB*MAXP*DD + 1] = s1;
        }
    }
}

// ===========================================================================
extern "C" void kernel_launch(void* const* d_in, const int* in_sizes, int n_in,
                              void* d_out, int out_size) {
    const float* latent = (const float*)d_in[0];
    const int*   mask   = (const int*)  d_in[1];
    const float* proj_w = (const float*)d_in[2];
    const float* proj_b = (const float*)d_in[3];
    const float* w1     = (const float*)d_in[4];
    const float* b1     = (const float*)d_in[5];
    const float* w2     = (const float*)d_in[6];
    const float* b2     = (const float*)d_in[7];
    float* out = (float*)d_out;

    cudaFuncSetAttribute(k_gemm, cudaFuncAttributeMaxDynamicSharedMemorySize, SM_DYN);

    // k_gemm is the 4th launch -> ncu window lands on it
    k_prep  <<< (NKT*FF*16 + 255)/256, 256 >>>(w1);
    k_cos   <<< M_TOTAL/32, 256 >>>(latent);
    k_pool  <<< BB, 256 >>>(latent, mask);
    k_gemm  <<< dim3(4, M_TOTAL/128), 256, SM_DYN >>>(b1, w2);
    k_patch1<<< dim3(DD/128, BB, KSP), 128 >>>(proj_w);
    k_rule  <<< 384, 256 >>>(b2, proj_b, out);
    k_final <<< 1, 32 >>>(out, out_size);
}

// round 13
// speedup vs baseline: 1.0013x; 1.0013x over previous
#include <cuda_runtime.h>
#include <cuda_bf16.h>
#include <cuda_fp16.h>
#include <cuda_fp8.h>
#include <math.h>
#include <stdint.h>

#define BB 8
#define SS 4096
#define DD 1024
#define FF 512
#define M_TOTAL (BB*SS)   // 32768
#define MAXP 8
#define NKT 16            // 1024/64 k-tiles
#define KSP 8             // split-k factor for patch GEMM
#define W1SCALE 64.0f
#define W1INV   0.015625f

// ---------------- device scratch ----------------
__device__ uint32_t g_Xq[(size_t)M_TOTAL * (DD/4)];      // 32 MB e4m3 tile-linear
__device__ uint32_t g_Bpk[NKT * FF * 16];                // 512 KB e4m3 tile-linear
__device__ float g_partial[M_TOTAL*8];
__device__ float g_norm2[M_TOTAL];
__device__ float g_dot[M_TOTAL];
__device__ float g_pooled[BB*MAXP*DD];
__device__ float g_ppart[KSP*BB*MAXP*DD];                // 2 MB split-k partials
__device__ int g_first, g_last;

// ---------------- helpers ----------------
__device__ __forceinline__ uint32_t s2u(const void* p){
    uint32_t a;
    asm("{ .reg .u64 t; cvta.to.shared.u64 t, %1; cvt.u32.u64 %0, t; }" : "=r"(a) : "l"(p));
    return a;
}
__device__ __forceinline__ void cp16(uint32_t dst, const void* src){
    asm volatile("cp.async.cg.shared.global [%0], [%1], 16;" :: "r"(dst), "l"(src) : "memory");
}
__device__ __forceinline__ void cp_commit(){ asm volatile("cp.async.commit_group;" ::: "memory"); }
__device__ __forceinline__ void cp_wait0(){ asm volatile("cp.async.wait_group 0;" ::: "memory"); }
__device__ __forceinline__ void cp_wait2(){ asm volatile("cp.async.wait_group 2;" ::: "memory"); }

__device__ __forceinline__ void mmaqh(unsigned* d, const unsigned* a, unsigned b0, unsigned b1){
    asm volatile(
      "mma.sync.aligned.m16n8k32.row.col.f16.e4m3.e4m3.f16 "
      "{%0,%1}, {%2,%3,%4,%5}, {%6,%7}, {%0,%1};\n"
      : "+r"(d[0]), "+r"(d[1])
      : "r"(a[0]), "r"(a[1]), "r"(a[2]), "r"(a[3]), "r"(b0), "r"(b1));
}
__device__ __forceinline__ void ldsm4(unsigned* r, uint32_t addr){
    asm volatile("ldmatrix.sync.aligned.m8n8.x4.shared.b16 {%0,%1,%2,%3}, [%4];"
                 : "=r"(r[0]), "=r"(r[1]), "=r"(r[2]), "=r"(r[3]) : "r"(addr));
}
__device__ __forceinline__ uint32_t pack4_e4m3(float x, float y, float z, float w){
    __nv_fp8x2_storage_t p0 = __nv_cvt_float2_to_fp8x2(make_float2(x, y), __NV_SATFINITE, __NV_E4M3);
    __nv_fp8x2_storage_t p1 = __nv_cvt_float2_to_fp8x2(make_float2(z, w), __NV_SATFINITE, __NV_E4M3);
    return ((uint32_t)p1 << 16) | (uint32_t)p0;
}

// ============ prep: pack 64*W1 -> [kt][n][64B] e4m3 rows (+ init) ==========
__global__ void k_prep(const float* __restrict__ W1){
    int idx = blockIdx.x*256 + threadIdx.x;    // 131072 words
    if (idx == 0){ g_first = 0x7fffffff; g_last = -1; }
    if (idx >= NKT*FF*16) return;
    int kt = idx >> 13;
    int wo = idx & 8191;
    int n  = wo >> 4;
    int ww = wo & 15;
    int k  = kt*64 + 4*ww;
    g_Bpk[idx] = pack4_e4m3(W1[(size_t)k*FF + n]     * W1SCALE,
                            W1[(size_t)(k+1)*FF + n] * W1SCALE,
                            W1[(size_t)(k+2)*FF + n] * W1SCALE,
                            W1[(size_t)(k+3)*FF + n] * W1SCALE);
}

// ===== k_conv: f32 -> e4m3 tile-linear pack (critical path, coalesced) =====
__global__ __launch_bounds__(256) void k_conv(const float* __restrict__ X){
    size_t t0 = (size_t)blockIdx.x*256 + threadIdx.x;   // 2M threads
    const float4* xp = (const float4*)X;
    #pragma unroll
    for (int j = 0; j < 4; j++){
        size_t di = t0 + (size_t)j*2097152;             // 8M words total
        int wi = (int)(di & 15);
        int rl = (int)((di >> 4) & 127);
        int kt = (int)((di >> 11) & 15);
        int mtile = (int)(di >> 15);
        float4 v = xp[((size_t)mtile*128 + rl)*256 + kt*16 + wi];
        g_Xq[di] = pack4_e4m3(v.x, v.y, v.z, v.w);
    }
}

// ===== k_norm: norms + adjacent dots (off critical path, overlapped) =======
__global__ __launch_bounds__(256) void k_norm(const float* __restrict__ X){
    int tid = threadIdx.x, w = tid>>5, lane = tid&31;
    int base = blockIdx.x*32 + w*4;
    const float4* xp = (const float4*)X;
    float4 a[8];
    size_t rb = (size_t)base*(DD/4);
    #pragma unroll
    for (int t = 0; t < 8; t++) a[t] = xp[rb + lane + t*32];
    #pragma unroll
    for (int j = 0; j < 4; j++){
        int s = base + j;
        float n2 = 0.f;
        #pragma unroll
        for (int t = 0; t < 8; t++)
            n2 += a[t].x*a[t].x + a[t].y*a[t].y + a[t].z*a[t].z + a[t].w*a[t].w;
        bool pv = ((s & (SS-1)) != (SS-1));
        float4 b[8];
        float dt = 0.f;
        if (pv){
            size_t rb2 = (size_t)(s+1)*(DD/4);
            #pragma unroll
            for (int t = 0; t < 8; t++){
                b[t] = xp[rb2 + lane + t*32];
                dt += a[t].x*b[t].x + a[t].y*b[t].y + a[t].z*b[t].z + a[t].w*b[t].w;
            }
        }
        #pragma unroll
        for (int o = 16; o > 0; o >>= 1){
            n2 += __shfl_xor_sync(0xffffffffu, n2, o);
            dt += __shfl_xor_sync(0xffffffffu, dt, o);
        }
        if (lane == 0){ g_norm2[s] = n2; if (pv) g_dot[s] = dt; }
        #pragma unroll
        for (int t = 0; t < 8; t++) a[t] = b[t];
    }
}

// ================= segment pooling: parallel mask scan + MLP sum ===========
__global__ __launch_bounds__(256) void k_pool(const float* __restrict__ X,
                                              const int* __restrict__ Mk){
    __shared__ float ssum[MAXP*DD];   // 32 KB
    __shared__ int   sseg[256];
    __shared__ int   scnt[MAXP];
    __shared__ int   swsum[8];
    int b = blockIdx.x;
    int tid = threadIdx.x, w = tid>>5, lane = tid&31;
    for (int i = tid; i < MAXP*DD; i += 256) ssum[i] = 0.f;
    if (tid < MAXP) scnt[tid] = 0;
    __syncthreads();
    const float* xb = X + (size_t)b*SS*DD;
    const int*   mb = Mk + (size_t)b*SS;

    int seg0 = 0;
    for (int base = 0; base < SS && seg0 < MAXP; base += 256){
        int m = mb[base + tid] != 0 ? 1 : 0;
        int v = m;
        #pragma unroll
        for (int o = 1; o < 32; o <<= 1){
            int n = __shfl_up_sync(0xffffffffu, v, o);
            if (lane >= o) v += n;
        }
        if (lane == 31) swsum[w] = v;
        __syncthreads();
        int woff = 0;
        #pragma unroll
        for (int j = 0; j < 8; j++) woff += (j < w) ? swsum[j] : 0;
        int seg = seg0 + woff + v - m;
        sseg[tid] = seg;
        if (seg < MAXP) atomicAdd(&scnt[seg], 1);
        int total = 0;
        #pragma unroll
        for (int j = 0; j < 8; j++) total += swsum[j];
        __syncthreads();
        for (int s = 0; s < 256; s++){
            int p = sseg[s];
            if (p >= MAXP) break;
            #pragma unroll
            for (int j = 0; j < 4; j++){
                int d = tid + j*256;
                ssum[p*DD + d] += xb[(size_t)(base + s)*DD + d];
            }
        }
        seg0 += total;
        __syncthreads();
    }
    #pragma unroll
    for (int p = 0; p < MAXP; p++){
        float inv = 1.f / (float)max(scnt[p], 1);
        #pragma unroll
        for (int j = 0; j < 4; j++){
            int d = tid + j*256;
            g_pooled[((size_t)b*MAXP + p)*DD + d] = ssum[p*DD + d] * inv;
        }
    }
}

// ===== GEMM: 4-buffer cp.async pipeline + fp8 QMMA f16acc, 2 CTAs/SM =======
#define ROWB 80
#define TILEB (128*ROWB)
#define SM_B1OFF (8*TILEB)
#define SM_W2OFF (SM_B1OFF + 2048)
#define SM_DYN   (SM_W2OFF + 2048)
__global__ __launch_bounds__(256, 2) void k_gemm(const float* __restrict__ b1,
                                                 const float* __restrict__ w2){
    extern __shared__ __align__(16) char dsm[];
    char* Abuf[4]; char* Bbuf[4];
    #pragma unroll
    for (int b = 0; b < 4; b++){
        Abuf[b] = dsm + b*TILEB;
        Bbuf[b] = dsm + 4*TILEB + b*TILEB;
    }
    float* b1s = (float*)(dsm + SM_B1OFF);
    float* w2s = (float*)(dsm + SM_W2OFF);

    const int nc  = blockIdx.x;
    const int mt0 = blockIdx.y;
    const int m0  = mt0 * 128;
    const int n0  = nc * 128;
    const int tid = threadIdx.x;
    const int warp = tid >> 5, lane = tid & 31;
    const int warpM = warp >> 1, warpN = warp & 1;
    const int lr = lane >> 2, qc = lane & 3;

    #pragma unroll
    for (int j = 0; j < 2; j++){
        b1s[tid + j*256] = b1[tid + j*256];
        w2s[tid + j*256] = w2[tid + j*256];
    }

    const int arow = warpM*32 + (lane & 7) + ((lane >> 3) & 1)*8;
    const int abyt = ((lane >> 4) & 1)*16;
    const int brow = warpN*64 + (lane & 7) + ((lane >> 4) & 1)*8;
    const int bbyt = ((lane >> 3) & 1)*16;
    const uint32_t aoff = (uint32_t)(arow*ROWB + abyt);
    const uint32_t boff = (uint32_t)(brow*ROWB + bbyt);

    const char* xsrc = (const char*)g_Xq + (size_t)mt0 * (NKT*128*64);
    const char* bsrc = (const char*)g_Bpk;

    auto stage = [&](int kt, int buf){
        uint32_t ad = s2u(Abuf[buf]);
        uint32_t bd = s2u(Bbuf[buf]);
        const char* xs = xsrc + (size_t)kt*(128*64);
        const char* bs = bsrc + ((size_t)kt*512 + n0)*64;
        #pragma unroll
        for (int i = 0; i < 2; i++){
            int g = tid + i*256;
            int row = g >> 2, cb = (g & 3)*16;
            cp16(ad + row*ROWB + cb, xs + row*64 + cb);
        }
        #pragma unroll
        for (int i = 0; i < 2; i++){
            int g = tid + i*256;
            int row = g >> 2, cb = (g & 3)*16;
            cp16(bd + row*ROWB + cb, bs + row*64 + cb);
        }
    };

    unsigned int acc[2][8][2];
    #pragma unroll
    for (int mt=0; mt<2; mt++)
      #pragma unroll
      for (int nt=0; nt<8; nt++){ acc[mt][nt][0] = 0u; acc[mt][nt][1] = 0u; }

    stage(0, 0); cp_commit();
    stage(1, 1); cp_commit();

    for (int kt = 0; kt < NKT; kt++){
        int buf = kt & 3;
        if (kt + 2 < NKT){
            stage(kt + 2, (kt + 2) & 3);
            cp_commit();
            cp_wait2();
        } else {
            cp_wait0();
        }
        __syncthreads();
        const uint32_t aA = s2u(Abuf[buf]) + aoff;
        const uint32_t bA = s2u(Bbuf[buf]) + boff;
        #pragma unroll
        for (int ks = 0; ks < 2; ks++){
            unsigned int a[2][4];
            ldsm4(a[0], aA + ks*32);
            ldsm4(a[1], aA + 16*ROWB + ks*32);
            unsigned int b[8][2];
            #pragma unroll
            for (int ntp = 0; ntp < 4; ntp++){
                unsigned int r[4];
                ldsm4(r, bA + ntp*16*ROWB + ks*32);
                b[2*ntp  ][0] = r[0]; b[2*ntp  ][1] = r[1];
                b[2*ntp+1][0] = r[2]; b[2*ntp+1][1] = r[3];
            }
            #pragma unroll
            for (int nt = 0; nt < 8; nt++){
                mmaqh(acc[0][nt], a[0], b[nt][0], b[nt][1]);
                mmaqh(acc[1][nt], a[1], b[nt][0], b[nt][1]);
            }
        }
    }

    float b1r[16], w2r[16];
    #pragma unroll
    for (int nt = 0; nt < 8; nt++){
        #pragma unroll
        for (int e = 0; e < 2; e++){
            int n = n0 + warpN*64 + nt*8 + qc*2 + e;
            b1r[nt*2+e] = b1s[n];
            w2r[nt*2+e] = w2s[n];
        }
    }
    #pragma unroll
    for (int mt = 0; mt < 2; mt++){
        float sA = 0.f, sB = 0.f;
        #pragma unroll
        for (int nt = 0; nt < 8; nt++){
            float2 vA = __half22float2(*(__half2*)&acc[mt][nt][0]);
            float2 vB = __half22float2(*(__half2*)&acc[mt][nt][1]);
            sA += fmaxf(vA.x * W1INV + b1r[nt*2+0], 0.f) * w2r[nt*2+0];
            sA += fmaxf(vA.y * W1INV + b1r[nt*2+1], 0.f) * w2r[nt*2+1];
            sB += fmaxf(vB.x * W1INV + b1r[nt*2+0], 0.f) * w2r[nt*2+0];
            sB += fmaxf(vB.y * W1INV + b1r[nt*2+1], 0.f) * w2r[nt*2+1];
        }
        sA += __shfl_xor_sync(0xffffffffu, sA, 1);
        sA += __shfl_xor_sync(0xffffffffu, sA, 2);
        sB += __shfl_xor_sync(0xffffffffu, sB, 1);
        sB += __shfl_xor_sync(0xffffffffu, sB, 2);
        if (qc == 0){
            int rA = m0 + warpM*32 + mt*16 + lr;
            g_partial[(size_t)rA*8     + nc*2 + warpN] = sA;
            g_partial[(size_t)(rA+8)*8 + nc*2 + warpN] = sB;
        }
    }
}

// ======== patch split-k pass 1: partial[ks][b][p][o] over 128-k chunk ======
__global__ __launch_bounds__(128) void k_patch1(const float* __restrict__ Pw){
    __shared__ float ps[MAXP*128];
    int oc = blockIdx.x, b = blockIdx.y, ks = blockIdx.z;
    int tid = threadIdx.x;
    #pragma unroll
    for (int j = 0; j < 8; j++){
        int e = tid + j*128;
        int p = e >> 7, d = e & 127;
        ps[p*128 + d] = g_pooled[((size_t)b*MAXP + p)*DD + ks*128 + d];
    }
    __syncthreads();
    int o = oc*128 + tid;
    float acc[MAXP];
    #pragma unroll
    for (int p = 0; p < MAXP; p++) acc[p] = 0.f;
    const float* pw = Pw + (size_t)(ks*128)*DD + o;
    #pragma unroll 4
    for (int d = 0; d < 128; d++){
        float w = pw[(size_t)d*DD];
        #pragma unroll
        for (int p = 0; p < MAXP; p++) acc[p] += ps[p*128 + d] * w;
    }
    #pragma unroll
    for (int p = 0; p < MAXP; p++)
        g_ppart[(((size_t)ks*BB + b)*MAXP + p)*DD + o] = acc[p];
}

// ======== fused: rules (blocks 0..127) + patch split-k reduce (128..383) ===
__global__ __launch_bounds__(256) void k_rule(const float* __restrict__ b2,
                                              const float* __restrict__ Pb,
                                              float* __restrict__ out){
    if (blockIdx.x >= 128){
        int i = (blockIdx.x - 128)*256 + threadIdx.x;
        int o = i & (DD-1);
        float s = Pb[o];
        #pragma unroll
        for (int ks = 0; ks < KSP; ks++)
            s += g_ppart[(size_t)ks*(BB*MAXP*DD) + i];
        out[i] = s;
        return;
    }
    __shared__ float sc[258];
    int base = blockIdx.x*256;
    int tid = threadIdx.x;
    int i = base + tid;
    float bb = __ldg(b2);
    {
        float l = bb;
        #pragma unroll
        for (int j = 0; j < 8; j++) l += g_partial[(size_t)i*8 + j];
        sc[tid + 2] = 1.f / (1.f + expf(-l));
    }
    if (tid < 2){
        int r = base - 2 + tid;
        float v = 0.f;
        if (r >= 0){
            float l = bb;
            #pragma unroll
            for (int j = 0; j < 8; j++) l += g_partial[(size_t)r*8 + j];
            v = 1.f / (1.f + expf(-l));
        }
        sc[tid] = v;
    }
    __syncthreads();
    int t = i & (SS-1);
    if (t < 2) return;
    float s0 = sc[tid+2], s1 = sc[tid+1], s2 = sc[tid];
    bool run = (s0 > 0.7f) && (s1 > 0.7f) && (s2 > 0.7f);
    float na = fmaxf(sqrtf(g_norm2[i-1]), 1e-8f);
    float nb = fmaxf(sqrtf(g_norm2[i]),   1e-8f);
    float cosv = g_dot[i-1] / (na * nb);
    bool cr = (cosv < 0.3f) && (s0 > 0.5f);
    if (run || cr){
        atomicMin(&g_first, t);
        atomicMax(&g_last,  t);
    }
}

// ================= finalize bounds =========================================
__global__ void k_final(float* __restrict__ out, int out_size){
    if (threadIdx.x == 0 && blockIdx.x == 0){
        int f = g_first, l = g_last;
        float s0 = -1.f, s1 = -1.f;
        if (f != 0x7fffffff){
            s0 = (float)max(0, f - 2);
            s1 = (float)min(SS - 1, l + 2);
        }
        if (out_size >= BB*MAXP*DD + 2){
            out[BB*MAXP*DD + 0] = s0;
            out[BB*MAXP*DD + 1] = s1;
        }
    }
}

// ===========================================================================
extern "C" void kernel_launch(void* const* d_in, const int* in_sizes, int n_in,
                              void* d_out, int out_size) {
    const float* latent = (const float*)d_in[0];
    const int*   mask   = (const int*)  d_in[1];
    const float* proj_w = (const float*)d_in[2];
    const float* proj_b = (const float*)d_in[3];
    const float* w1     = (const float*)d_in[4];
    const float* b1     = (const float*)d_in[5];
    const float* w2     = (const float*)d_in[6];
    const float* b2     = (const float*)d_in[7];
    float* out = (float*)d_out;

    static cudaStream_t s2 = nullptr;
    static cudaEvent_t eF = nullptr, eJ = nullptr;
    if (s2 == nullptr){
        cudaStreamCreateWithFlags(&s2, cudaStreamNonBlocking);
        cudaEventCreateWithFlags(&eF, cudaEventDisableTiming);
        cudaEventCreateWithFlags(&eJ, cudaEventDisableTiming);
        cudaFuncSetAttribute(k_gemm, cudaFuncAttributeMaxDynamicSharedMemorySize, SM_DYN);
    }

    // fork: side stream joins the capture DAG
    cudaEventRecord(eF, 0);
    cudaStreamWaitEvent(s2, eF, 0);

    // main chain (critical path); k_gemm is the 4th kernel launch for ncu
    k_prep  <<< (NKT*FF*16 + 255)/256, 256 >>>(w1);
    k_conv  <<< 8192, 256 >>>(latent);
    k_pool  <<< BB, 256, 0, s2 >>>(latent, mask);
    k_gemm  <<< dim3(4, M_TOTAL/128), 256, SM_DYN >>>(b1, w2);
    k_patch1<<< dim3(DD/128, BB, KSP), 128, 0, s2 >>>(proj_w);
    k_norm  <<< M_TOTAL/32, 256, 0, s2 >>>(latent);

    // join: rule needs gemm partials (main) + patch partials & norms (s2)
    cudaEventRecord(eJ, s2);
    cudaStreamWaitEvent(0, eJ, 0);
    k_rule  <<< 384, 256 >>>(b2, proj_b, out);
    k_final <<< 1, 32 >>>(out, out_size);
}

// round 14
// speedup vs baseline: 1.0484x; 1.0470x over previous
#include <cuda_runtime.h>
#include <cuda_bf16.h>
#include <cuda_fp16.h>
#include <cuda_fp8.h>
#include <math.h>
#include <stdint.h>

#define BB 8
#define SS 4096
#define DD 1024
#define FF 512
#define M_TOTAL (BB*SS)   // 32768
#define MAXP 8
#define NKT 16            // 1024/64 k-tiles
#define KSP 8             // split-k factor for patch GEMM
#define W1SCALE 64.0f
#define W1INV   0.015625f

// ---------------- device scratch ----------------
__device__ uint32_t g_Xq[(size_t)M_TOTAL * (DD/4)];      // 32 MB e4m3 tile-linear
__device__ uint32_t g_Bpk[NKT * FF * 16];                // 512 KB e4m3 tile-linear
__device__ float g_partial[M_TOTAL*8];
__device__ float g_norm2[M_TOTAL];
__device__ float g_dot[M_TOTAL];
__device__ float g_pooled[BB*MAXP*DD];
__device__ float g_ppart[KSP*BB*MAXP*DD];                // 2 MB split-k partials
__device__ int g_first, g_last;

// ---------------- helpers ----------------
__device__ __forceinline__ uint32_t s2u(const void* p){
    uint32_t a;
    asm("{ .reg .u64 t; cvta.to.shared.u64 t, %1; cvt.u32.u64 %0, t; }" : "=r"(a) : "l"(p));
    return a;
}
__device__ __forceinline__ void cp16(uint32_t dst, const void* src){
    asm volatile("cp.async.cg.shared.global [%0], [%1], 16;" :: "r"(dst), "l"(src) : "memory");
}
__device__ __forceinline__ void cp_commit(){ asm volatile("cp.async.commit_group;" ::: "memory"); }
__device__ __forceinline__ void cp_wait0(){ asm volatile("cp.async.wait_group 0;" ::: "memory"); }
__device__ __forceinline__ void cp_wait2(){ asm volatile("cp.async.wait_group 2;" ::: "memory"); }

__device__ __forceinline__ void mmaqh(unsigned* d, const unsigned* a, unsigned b0, unsigned b1){
    asm volatile(
      "mma.sync.aligned.m16n8k32.row.col.f16.e4m3.e4m3.f16 "
      "{%0,%1}, {%2,%3,%4,%5}, {%6,%7}, {%0,%1};\n"
      : "+r"(d[0]), "+r"(d[1])
      : "r"(a[0]), "r"(a[1]), "r"(a[2]), "r"(a[3]), "r"(b0), "r"(b1));
}
__device__ __forceinline__ void ldsm4(unsigned* r, uint32_t addr){
    asm volatile("ldmatrix.sync.aligned.m8n8.x4.shared.b16 {%0,%1,%2,%3}, [%4];"
                 : "=r"(r[0]), "=r"(r[1]), "=r"(r[2]), "=r"(r[3]) : "r"(addr));
}
__device__ __forceinline__ uint32_t pack4_e4m3(float x, float y, float z, float w){
    __nv_fp8x2_storage_t p0 = __nv_cvt_float2_to_fp8x2(make_float2(x, y), __NV_SATFINITE, __NV_E4M3);
    __nv_fp8x2_storage_t p1 = __nv_cvt_float2_to_fp8x2(make_float2(z, w), __NV_SATFINITE, __NV_E4M3);
    return ((uint32_t)p1 << 16) | (uint32_t)p0;
}

// ============ prep: pack 64*W1 -> [kt][n][64B] e4m3 rows (+ init) ==========
__global__ void k_prep(const float* __restrict__ W1){
    int idx = blockIdx.x*256 + threadIdx.x;    // 131072 words
    if (idx == 0){ g_first = 0x7fffffff; g_last = -1; }
    if (idx >= NKT*FF*16) return;
    int kt = idx >> 13;
    int wo = idx & 8191;
    int n  = wo >> 4;
    int ww = wo & 15;
    int k  = kt*64 + 4*ww;
    g_Bpk[idx] = pack4_e4m3(W1[(size_t)k*FF + n]     * W1SCALE,
                            W1[(size_t)(k+1)*FF + n] * W1SCALE,
                            W1[(size_t)(k+2)*FF + n] * W1SCALE,
                            W1[(size_t)(k+3)*FF + n] * W1SCALE);
}

// ===== k_conv: f32 -> e4m3 tile-linear pack (critical path, coalesced) =====
__global__ __launch_bounds__(256) void k_conv(const float* __restrict__ X){
    size_t t0 = (size_t)blockIdx.x*256 + threadIdx.x;   // 2M threads
    const float4* xp = (const float4*)X;
    #pragma unroll
    for (int j = 0; j < 4; j++){
        size_t di = t0 + (size_t)j*2097152;             // 8M words total
        int wi = (int)(di & 15);
        int rl = (int)((di >> 4) & 127);
        int kt = (int)((di >> 11) & 15);
        int mtile = (int)(di >> 15);
        float4 v = xp[((size_t)mtile*128 + rl)*256 + kt*16 + wi];
        g_Xq[di] = pack4_e4m3(v.x, v.y, v.z, v.w);
    }
}

// ===== k_norm: norms + adjacent dots (off critical path, overlapped) =======
__global__ __launch_bounds__(256) void k_norm(const float* __restrict__ X){
    int tid = threadIdx.x, w = tid>>5, lane = tid&31;
    int base = blockIdx.x*32 + w*4;
    const float4* xp = (const float4*)X;
    float4 a[8];
    size_t rb = (size_t)base*(DD/4);
    #pragma unroll
    for (int t = 0; t < 8; t++) a[t] = xp[rb + lane + t*32];
    #pragma unroll
    for (int j = 0; j < 4; j++){
        int s = base + j;
        float n2 = 0.f;
        #pragma unroll
        for (int t = 0; t < 8; t++)
            n2 += a[t].x*a[t].x + a[t].y*a[t].y + a[t].z*a[t].z + a[t].w*a[t].w;
        bool pv = ((s & (SS-1)) != (SS-1));
        float4 b[8];
        float dt = 0.f;
        if (pv){
            size_t rb2 = (size_t)(s+1)*(DD/4);
            #pragma unroll
            for (int t = 0; t < 8; t++){
                b[t] = xp[rb2 + lane + t*32];
                dt += a[t].x*b[t].x + a[t].y*b[t].y + a[t].z*b[t].z + a[t].w*b[t].w;
            }
        }
        #pragma unroll
        for (int o = 16; o > 0; o >>= 1){
            n2 += __shfl_xor_sync(0xffffffffu, n2, o);
            dt += __shfl_xor_sync(0xffffffffu, dt, o);
        }
        if (lane == 0){ g_norm2[s] = n2; if (pv) g_dot[s] = dt; }
        #pragma unroll
        for (int t = 0; t < 8; t++) a[t] = b[t];
    }
}

// ================= segment pooling: parallel mask scan + MLP sum ===========
__global__ __launch_bounds__(256) void k_pool(const float* __restrict__ X,
                                              const int* __restrict__ Mk){
    __shared__ float ssum[MAXP*DD];   // 32 KB
    __shared__ int   sseg[256];
    __shared__ int   scnt[MAXP];
    __shared__ int   swsum[8];
    int b = blockIdx.x;
    int tid = threadIdx.x, w = tid>>5, lane = tid&31;
    for (int i = tid; i < MAXP*DD; i += 256) ssum[i] = 0.f;
    if (tid < MAXP) scnt[tid] = 0;
    __syncthreads();
    const float* xb = X + (size_t)b*SS*DD;
    const int*   mb = Mk + (size_t)b*SS;

    int seg0 = 0;
    for (int base = 0; base < SS && seg0 < MAXP; base += 256){
        int m = mb[base + tid] != 0 ? 1 : 0;
        int v = m;
        #pragma unroll
        for (int o = 1; o < 32; o <<= 1){
            int n = __shfl_up_sync(0xffffffffu, v, o);
            if (lane >= o) v += n;
        }
        if (lane == 31) swsum[w] = v;
        __syncthreads();
        int woff = 0;
        #pragma unroll
        for (int j = 0; j < 8; j++) woff += (j < w) ? swsum[j] : 0;
        int seg = seg0 + woff + v - m;
        sseg[tid] = seg;
        if (seg < MAXP) atomicAdd(&scnt[seg], 1);
        int total = 0;
        #pragma unroll
        for (int j = 0; j < 8; j++) total += swsum[j];
        __syncthreads();
        for (int s = 0; s < 256; s++){
            int p = sseg[s];
            if (p >= MAXP) break;
            #pragma unroll
            for (int j = 0; j < 4; j++){
                int d = tid + j*256;
                ssum[p*DD + d] += xb[(size_t)(base + s)*DD + d];
            }
        }
        seg0 += total;
        __syncthreads();
    }
    #pragma unroll
    for (int p = 0; p < MAXP; p++){
        float inv = 1.f / (float)max(scnt[p], 1);
        #pragma unroll
        for (int j = 0; j < 4; j++){
            int d = tid + j*256;
            g_pooled[((size_t)b*MAXP + p)*DD + d] = ssum[p*DD + d] * inv;
        }
    }
}

// ===== GEMM: 4-buffer cp.async pipeline + fp8 QMMA f16acc (regs uncapped) ==
#define ROWB 80
#define TILEB (128*ROWB)
#define SM_B1OFF (8*TILEB)
#define SM_W2OFF (SM_B1OFF + 2048)
#define SM_DYN   (SM_W2OFF + 2048)
__global__ __launch_bounds__(256) void k_gemm(const float* __restrict__ b1,
                                              const float* __restrict__ w2){
    extern __shared__ __align__(16) char dsm[];
    char* Abuf[4]; char* Bbuf[4];
    #pragma unroll
    for (int b = 0; b < 4; b++){
        Abuf[b] = dsm + b*TILEB;
        Bbuf[b] = dsm + 4*TILEB + b*TILEB;
    }
    float* b1s = (float*)(dsm + SM_B1OFF);
    float* w2s = (float*)(dsm + SM_W2OFF);

    const int nc  = blockIdx.x;
    const int mt0 = blockIdx.y;
    const int m0  = mt0 * 128;
    const int n0  = nc * 128;
    const int tid = threadIdx.x;
    const int warp = tid >> 5, lane = tid & 31;
    const int warpM = warp >> 1, warpN = warp & 1;
    const int lr = lane >> 2, qc = lane & 3;

    #pragma unroll
    for (int j = 0; j < 2; j++){
        b1s[tid + j*256] = b1[tid + j*256];
        w2s[tid + j*256] = w2[tid + j*256];
    }

    const int arow = warpM*32 + (lane & 7) + ((lane >> 3) & 1)*8;
    const int abyt = ((lane >> 4) & 1)*16;
    const int brow = warpN*64 + (lane & 7) + ((lane >> 4) & 1)*8;
    const int bbyt = ((lane >> 3) & 1)*16;
    const uint32_t aoff = (uint32_t)(arow*ROWB + abyt);
    const uint32_t boff = (uint32_t)(brow*ROWB + bbyt);

    const char* xsrc = (const char*)g_Xq + (size_t)mt0 * (NKT*128*64);
    const char* bsrc = (const char*)g_Bpk;

    auto stage = [&](int kt, int buf){
        uint32_t ad = s2u(Abuf[buf]);
        uint32_t bd = s2u(Bbuf[buf]);
        const char* xs = xsrc + (size_t)kt*(128*64);
        const char* bs = bsrc + ((size_t)kt*512 + n0)*64;
        #pragma unroll
        for (int i = 0; i < 2; i++){
            int g = tid + i*256;
            int row = g >> 2, cb = (g & 3)*16;
            cp16(ad + row*ROWB + cb, xs + row*64 + cb);
        }
        #pragma unroll
        for (int i = 0; i < 2; i++){
            int g = tid + i*256;
            int row = g >> 2, cb = (g & 3)*16;
            cp16(bd + row*ROWB + cb, bs + row*64 + cb);
        }
    };

    unsigned int acc[2][8][2];
    #pragma unroll
    for (int mt=0; mt<2; mt++)
      #pragma unroll
      for (int nt=0; nt<8; nt++){ acc[mt][nt][0] = 0u; acc[mt][nt][1] = 0u; }

    stage(0, 0); cp_commit();
    stage(1, 1); cp_commit();

    for (int kt = 0; kt < NKT; kt++){
        int buf = kt & 3;
        if (kt + 2 < NKT){
            stage(kt + 2, (kt + 2) & 3);
            cp_commit();
            cp_wait2();
        } else {
            cp_wait0();
        }
        __syncthreads();
        const uint32_t aA = s2u(Abuf[buf]) + aoff;
        const uint32_t bA = s2u(Bbuf[buf]) + boff;
        #pragma unroll
        for (int ks = 0; ks < 2; ks++){
            unsigned int a[2][4];
            ldsm4(a[0], aA + ks*32);
            ldsm4(a[1], aA + 16*ROWB + ks*32);
            unsigned int b[8][2];
            #pragma unroll
            for (int ntp = 0; ntp < 4; ntp++){
                unsigned int r[4];
                ldsm4(r, bA + ntp*16*ROWB + ks*32);
                b[2*ntp  ][0] = r[0]; b[2*ntp  ][1] = r[1];
                b[2*ntp+1][0] = r[2]; b[2*ntp+1][1] = r[3];
            }
            #pragma unroll
            for (int nt = 0; nt < 8; nt++){
                mmaqh(acc[0][nt], a[0], b[nt][0], b[nt][1]);
                mmaqh(acc[1][nt], a[1], b[nt][0], b[nt][1]);
            }
        }
    }

    float b1r[16], w2r[16];
    #pragma unroll
    for (int nt = 0; nt < 8; nt++){
        #pragma unroll
        for (int e = 0; e < 2; e++){
            int n = n0 + warpN*64 + nt*8 + qc*2 + e;
            b1r[nt*2+e] = b1s[n];
            w2r[nt*2+e] = w2s[n];
        }
    }
    #pragma unroll
    for (int mt = 0; mt < 2; mt++){
        float sA = 0.f, sB = 0.f;
        #pragma unroll
        for (int nt = 0; nt < 8; nt++){
            float2 vA = __half22float2(*(__half2*)&acc[mt][nt][0]);
            float2 vB = __half22float2(*(__half2*)&acc[mt][nt][1]);
            sA += fmaxf(vA.x * W1INV + b1r[nt*2+0], 0.f) * w2r[nt*2+0];
            sA += fmaxf(vA.y * W1INV + b1r[nt*2+1], 0.f) * w2r[nt*2+1];
            sB += fmaxf(vB.x * W1INV + b1r[nt*2+0], 0.f) * w2r[nt*2+0];
            sB += fmaxf(vB.y * W1INV + b1r[nt*2+1], 0.f) * w2r[nt*2+1];
        }
        sA += __shfl_xor_sync(0xffffffffu, sA, 1);
        sA += __shfl_xor_sync(0xffffffffu, sA, 2);
        sB += __shfl_xor_sync(0xffffffffu, sB, 1);
        sB += __shfl_xor_sync(0xffffffffu, sB, 2);
        if (qc == 0){
            int rA = m0 + warpM*32 + mt*16 + lr;
            g_partial[(size_t)rA*8     + nc*2 + warpN] = sA;
            g_partial[(size_t)(rA+8)*8 + nc*2 + warpN] = sB;
        }
    }
}

// ======== patch split-k pass 1: partial[ks][b][p][o] over 128-k chunk ======
__global__ __launch_bounds__(128) void k_patch1(const float* __restrict__ Pw){
    __shared__ float ps[MAXP*128];
    int oc = blockIdx.x, b = blockIdx.y, ks = blockIdx.z;
    int tid = threadIdx.x;
    #pragma unroll
    for (int j = 0; j < 8; j++){
        int e = tid + j*128;
        int p = e >> 7, d = e & 127;
        ps[p*128 + d] = g_pooled[((size_t)b*MAXP + p)*DD + ks*128 + d];
    }
    __syncthreads();
    int o = oc*128 + tid;
    float acc[MAXP];
    #pragma unroll
    for (int p = 0; p < MAXP; p++) acc[p] = 0.f;
    const float* pw = Pw + (size_t)(ks*128)*DD + o;
    #pragma unroll 4
    for (int d = 0; d < 128; d++){
        float w = pw[(size_t)d*DD];
        #pragma unroll
        for (int p = 0; p < MAXP; p++) acc[p] += ps[p*128 + d] * w;
    }
    #pragma unroll
    for (int p = 0; p < MAXP; p++)
        g_ppart[(((size_t)ks*BB + b)*MAXP + p)*DD + o] = acc[p];
}

// ======== fused: rules (blocks 0..127) + patch split-k reduce (128..383) ===
__global__ __launch_bounds__(256) void k_rule(const float* __restrict__ b2,
                                              const float* __restrict__ Pb,
                                              float* __restrict__ out){
    if (blockIdx.x >= 128){
        int i = (blockIdx.x - 128)*256 + threadIdx.x;
        int o = i & (DD-1);
        float s = Pb[o];
        #pragma unroll
        for (int ks = 0; ks < KSP; ks++)
            s += g_ppart[(size_t)ks*(BB*MAXP*DD) + i];
        out[i] = s;
        return;
    }
    __shared__ float sc[258];
    int base = blockIdx.x*256;
    int tid = threadIdx.x;
    int i = base + tid;
    float bb = __ldg(b2);
    {
        float l = bb;
        #pragma unroll
        for (int j = 0; j < 8; j++) l += g_partial[(size_t)i*8 + j];
        sc[tid + 2] = 1.f / (1.f + expf(-l));
    }
    if (tid < 2){
        int r = base - 2 + tid;
        float v = 0.f;
        if (r >= 0){
            float l = bb;
            #pragma unroll
            for (int j = 0; j < 8; j++) l += g_partial[(size_t)r*8 + j];
            v = 1.f / (1.f + expf(-l));
        }
        sc[tid] = v;
    }
    __syncthreads();
    int t = i & (SS-1);
    if (t < 2) return;
    float s0 = sc[tid+2], s1 = sc[tid+1], s2 = sc[tid];
    bool run = (s0 > 0.7f) && (s1 > 0.7f) && (s2 > 0.7f);
    float na = fmaxf(sqrtf(g_norm2[i-1]), 1e-8f);
    float nb = fmaxf(sqrtf(g_norm2[i]),   1e-8f);
    float cosv = g_dot[i-1] / (na * nb);
    bool cr = (cosv < 0.3f) && (s0 > 0.5f);
    if (run || cr){
        atomicMin(&g_first, t);
        atomicMax(&g_last,  t);
    }
}

// ================= finalize bounds =========================================
__global__ void k_final(float* __restrict__ out, int out_size){
    if (threadIdx.x == 0 && blockIdx.x == 0){
        int f = g_first, l = g_last;
        float s0 = -1.f, s1 = -1.f;
        if (f != 0x7fffffff){
            s0 = (float)max(0, f - 2);
            s1 = (float)min(SS - 1, l + 2);
        }
        if (out_size >= BB*MAXP*DD + 2){
            out[BB*MAXP*DD + 0] = s0;
            out[BB*MAXP*DD + 1] = s1;
        }
    }
}

// ===========================================================================
extern "C" void kernel_launch(void* const* d_in, const int* in_sizes, int n_in,
                              void* d_out, int out_size) {
    const float* latent = (const float*)d_in[0];
    const int*   mask   = (const int*)  d_in[1];
    const float* proj_w = (const float*)d_in[2];
    const float* proj_b = (const float*)d_in[3];
    const float* w1     = (const float*)d_in[4];
    const float* b1     = (const float*)d_in[5];
    const float* w2     = (const float*)d_in[6];
    const float* b2     = (const float*)d_in[7];
    float* out = (float*)d_out;

    static cudaStream_t s2 = nullptr;
    static cudaEvent_t eF = nullptr, eJ = nullptr;
    if (s2 == nullptr){
        cudaStreamCreateWithFlags(&s2, cudaStreamNonBlocking);
        cudaEventCreateWithFlags(&eF, cudaEventDisableTiming);
        cudaEventCreateWithFlags(&eJ, cudaEventDisableTiming);
        cudaFuncSetAttribute(k_gemm, cudaFuncAttributeMaxDynamicSharedMemorySize, SM_DYN);
    }

    // fork: side stream joins the capture DAG
    cudaEventRecord(eF, 0);
    cudaStreamWaitEvent(s2, eF, 0);

    // main chain (critical path); k_gemm is the 4th kernel launch for ncu
    k_prep  <<< (NKT*FF*16 + 255)/256, 256 >>>(w1);
    k_conv  <<< 8192, 256 >>>(latent);
    k_pool  <<< BB, 256, 0, s2 >>>(latent, mask);
    k_gemm  <<< dim3(4, M_TOTAL/128), 256, SM_DYN >>>(b1, w2);
    k_patch1<<< dim3(DD/128, BB, KSP), 128, 0, s2 >>>(proj_w);
    k_norm  <<< M_TOTAL/32, 256, 0, s2 >>>(latent);

    // join: rule needs gemm partials (main) + patch partials & norms (s2)
    cudaEventRecord(eJ, s2);
    cudaStreamWaitEvent(0, eJ, 0);
    k_rule  <<< 384, 256 >>>(b2, proj_b, out);
    k_final <<< 1, 32 >>>(out, out_size);
}